// round 15
// baseline (speedup 1.0000x reference)
#include <cuda_runtime.h>
#include <cuda_bf16.h>
#include <cstdint>

#define NN 100000
#define EE 1600000
#define GG 512
#define NB 98           // ceil(NN/1024)
#define NT2 1563        // ceil(NN/64)
#define PA2 72          // stage plane pitch (bf16) for 64-wide K chunks
#define APL 9216        // A plane bytes: 64 * 72 * 2
#define BPL 18432       // B plane bytes: 128 * 72 * 2
#define BUF 55296       // stage buffer: Ah+Al+Bh+Bl
#define OAH 0
#define OAL APL
#define OBH (2 * APL)
#define OBL (2 * APL + BPL)
#define HPA 216         // hid smem pitch (bf16): 432B rows, conflict-free ldmatrix
#define HPLB 27648      // hid plane bytes: 64 * 216 * 2

// fp32 state (unpadded 100-float rows: 40MB planes stay L2-resident; ALWAYS relu'd)
__device__ __align__(16) float g_h[NN * 100];
__device__ __align__(16) float g_xd[NN * 100];
// bf16 split planes (GEMM operands)
__device__ __align__(16) __nv_bfloat16 g_aggh[NN * 128];
__device__ __align__(16) __nv_bfloat16 g_aggl[NN * 128];
__device__ __align__(16) __nv_bfloat16 g_w1h[3][256 * 128];
__device__ __align__(16) __nv_bfloat16 g_w1l[3][256 * 128];
__device__ __align__(16) __nv_bfloat16 g_w2h[3][128 * 256];
__device__ __align__(16) __nv_bfloat16 g_w2l[3][128 * 256];
// graph structure
__device__ int   g_cnt[NN];
__device__ int   g_off[NN];
__device__ int   g_cur[NN];
__device__ int   g_csr[EE];
__device__ unsigned long long g_desc[NB];
__device__ int   g_cntg[GG];
__device__ int   g_goff[GG + 1];
__device__ int   g_gcur[GG];
__device__ int   g_nlist[NN];
// readout
__device__ float g_enc[GG * 200];

__device__ __forceinline__ int clampi(int v, int hi) {
    return v < 0 ? 0 : (v >= hi ? hi - 1 : v);
}

__device__ __forceinline__ uint32_t smem_u32(const void* p) {
    uint32_t a;
    asm("{ .reg .u64 t; cvta.to.shared.u64 t, %1; cvt.u32.u64 %0, t; }" : "=r"(a) : "l"(p));
    return a;
}

__device__ __forceinline__ void bsplit(float v, __nv_bfloat16& h, __nv_bfloat16& l) {
    h = __float2bfloat16(v);
    l = __float2bfloat16(v - __bfloat162float(h));
}

__device__ __forceinline__ float fexp2(float v) {
    float r;
    asm("ex2.approx.f32 %0, %1;" : "=f"(r) : "f"(v));
    return r;
}

#define LDSM4(r, a) \
    asm volatile("ldmatrix.sync.aligned.m8n8.x4.shared.b16 {%0,%1,%2,%3},[%4];" \
        : "=r"((r)[0]), "=r"((r)[1]), "=r"((r)[2]), "=r"((r)[3]) : "r"(a))

__device__ __forceinline__ void mma_bf16(float* c, const uint32_t* a, const uint32_t* b) {
    asm volatile(
        "mma.sync.aligned.m16n8k16.row.col.f32.bf16.bf16.f32 "
        "{%0,%1,%2,%3}, {%4,%5,%6,%7}, {%8,%9}, {%0,%1,%2,%3};"
        : "+f"(c[0]), "+f"(c[1]), "+f"(c[2]), "+f"(c[3])
        : "r"(a[0]), "r"(a[1]), "r"(a[2]), "r"(a[3]), "r"(b[0]), "r"(b[1]));
}

// A fragment (non-trans x4) on [m][k], parametric pitch
__device__ __forceinline__ uint32_t a_addr(uint32_t base, int rbase, int k0, int lane, int pitch) {
    int grp = lane >> 3, wi = lane & 7;
    int r = rbase + ((grp & 1) << 3) + wi;
    int c = k0 + ((grp >> 1) << 3);
    return base + ((r * pitch + c) << 1);
}
// B fragment (non-trans x4) on [n][k] at stage pitch PA2
__device__ __forceinline__ uint32_t b_addr(uint32_t base, int nbase, int k0, int lane) {
    int grp = lane >> 3, wi = lane & 7;
    int nr = nbase + ((grp >> 1) << 3) + wi;
    int c = k0 + ((grp & 1) << 3);
    return base + ((nr * PA2 + c) << 1);
}

// ================= launch #1: fused lin10 + histograms =================

__global__ void k_pre(const float* __restrict__ x,
                      const float* __restrict__ ws, const float* __restrict__ bs,
                      const float* __restrict__ wd, const float* __restrict__ bd,
                      const int* __restrict__ ei, const int* __restrict__ batch) {
    __shared__ float sws[1000], sbs[100], swd[1000], sbd[100];
    int tid = threadIdx.x;
    int gi = blockIdx.x * blockDim.x + tid;
    bool doLin = (blockIdx.x * blockDim.x) < NN;   // block-uniform
    if (doLin) {
        for (int i = tid; i < 1000; i += blockDim.x) { sws[i] = ws[i]; swd[i] = wd[i]; }
        for (int i = tid; i < 100; i += blockDim.x)  { sbs[i] = bs[i]; sbd[i] = bd[i]; }
    }
    if (gi < EE) atomicAdd(&g_cnt[clampi(ei[EE + gi], NN)], 1);
    if (gi < NN) atomicAdd(&g_cntg[clampi(batch[gi], GG)], 1);
    if (!doLin) return;
    __syncthreads();
    if (gi >= NN) return;
    float xr[10];
#pragma unroll
    for (int k = 0; k < 10; k++) xr[k] = x[gi * 10 + k];
    for (int o = 0; o < 100; o++) {
        float a = sbs[o], b = sbd[o];
#pragma unroll
        for (int k = 0; k < 10; k++) {
            a += xr[k] * sws[o * 10 + k];
            b += xr[k] * swd[o * 10 + k];
        }
        g_h[gi * 100 + o] = fmaxf(a, 0.0f);   // lin_src output only consumed via relu()
        g_xd[gi * 100 + o] = b;
    }
}

// ================= launch #2: decoupled-lookback scan =================

__global__ void k_scan() {
    int b = blockIdx.x, tid = threadIdx.x;
    int i = b * 1024 + tid;
    int v = (i < NN) ? g_cnt[i] : 0;
    int lane = tid & 31, w = tid >> 5;
    int x = v;
#pragma unroll
    for (int o = 1; o < 32; o <<= 1) {
        int t = __shfl_up_sync(0xffffffffu, x, o);
        if (lane >= o) x += t;
    }
    __shared__ int ws[32];
    if (lane == 31) ws[w] = x;
    __syncthreads();
    if (tid < 32) {
        int s = ws[tid], y = s;
#pragma unroll
        for (int o = 1; o < 32; o <<= 1) {
            int t = __shfl_up_sync(0xffffffffu, y, o);
            if (tid >= o) y += t;
        }
        ws[tid] = y - s;
    }
    __syncthreads();
    int incl = ws[w] + x;
    __shared__ int s_total, s_prefix;
    if (tid == 1023) s_total = incl;
    __syncthreads();
    if (tid == 0) {
        int total = s_total;
        if (b == 0) {
            *(volatile unsigned long long*)&g_desc[0] = (2ull << 32) | (unsigned)total;
            s_prefix = 0;
        } else {
            *(volatile unsigned long long*)&g_desc[b] = (1ull << 32) | (unsigned)total;
            int pre = 0, j = b - 1;
            while (true) {
                unsigned long long d2 = *(volatile unsigned long long*)&g_desc[j];
                unsigned st = (unsigned)(d2 >> 32);
                if (st == 0) continue;
                pre += (int)(unsigned)d2;
                if (st == 2) break;
                j--;
            }
            *(volatile unsigned long long*)&g_desc[b] = (2ull << 32) | (unsigned)(pre + total);
            s_prefix = pre;
        }
    }
    __syncthreads();
    int excl = s_prefix + incl - v;
    if (i < NN) { g_off[i] = excl; g_cur[i] = excl; }
}

// ================= launch #3: scatter (+ reset for replay) =================

__global__ void k_scatter(const int* __restrict__ ei) {
    int e = blockIdx.x * blockDim.x + threadIdx.x;
    if (e < EE) {
        int d = clampi(ei[EE + e], NN);
        int p = atomicAdd(&g_cur[d], 1);
        if (p >= 0 && p < EE) g_csr[p] = clampi(ei[e], NN);
    }
    if (e < NN) g_cnt[e] = 0;
    if (e < NB) g_desc[e] = 0ull;
}

// ================= launch #4 (PROFILED): softmax aggregation =================
// g_h is always relu'd -> no per-edge fmax. Σ e·(r+ε) = Σ e·r + ε·Σ e (exact).

__global__ void k_agg(int use_gxd) {
    int w = (blockIdx.x * blockDim.x + threadIdx.x) >> 5;
    int lane = threadIdx.x & 31;
    if (w >= NN) return;
    if (lane >= 25) {  // zero K-pad cols 100..127
        int c = 100 + (lane - 25) * 4;
        *(uint2*)&g_aggh[(size_t)w * 128 + c] = make_uint2(0u, 0u);
        *(uint2*)&g_aggl[(size_t)w * 128 + c] = make_uint2(0u, 0u);
        return;
    }
    int start = g_off[w];
    int end = (w < NN - 1) ? g_off[w + 1] : EE;
    const char* hbase = (const char*)g_h;
    const float4* xd4 = use_gxd ? (const float4*)g_xd : (const float4*)g_h;
    const float EPS_MSG = 1e-7f;
    const float EPS_SM = 1e-16f;
    const float L2E = 1.44269504f;
    const float CLMP = 115.0f;
    uint32_t boff = (uint32_t)lane * 16u;

    float4 d = make_float4(0, 0, 0, 0);
    float4 nr = make_float4(0, 0, 0, 0);
    for (int i = start; i < end; i++) {
        uint32_t s = (uint32_t)g_csr[i];
        float4 v = *(const float4*)(hbase + s * 400u + boff);
        float e0 = fexp2(fminf(v.x * L2E, CLMP));
        float e1 = fexp2(fminf(v.y * L2E, CLMP));
        float e2 = fexp2(fminf(v.z * L2E, CLMP));
        float e3 = fexp2(fminf(v.w * L2E, CLMP));
        d.x += e0; nr.x = fmaf(e0, v.x, nr.x);
        d.y += e1; nr.y = fmaf(e1, v.y, nr.y);
        d.z += e2; nr.z = fmaf(e2, v.z, nr.z);
        d.w += e3; nr.w = fmaf(e3, v.w, nr.w);
    }
    float4 xv = xd4[(size_t)w * 25 + lane];
    float o0 = fmaf(EPS_MSG, d.x, nr.x) / (d.x + EPS_SM) + xv.x;
    float o1 = fmaf(EPS_MSG, d.y, nr.y) / (d.y + EPS_SM) + xv.y;
    float o2 = fmaf(EPS_MSG, d.z, nr.z) / (d.z + EPS_SM) + xv.z;
    float o3 = fmaf(EPS_MSG, d.w, nr.w) / (d.w + EPS_SM) + xv.w;
    __nv_bfloat16 hb[4], lb[4];
    bsplit(o0, hb[0], lb[0]); bsplit(o1, hb[1], lb[1]);
    bsplit(o2, hb[2], lb[2]); bsplit(o3, hb[3], lb[3]);
    size_t idx = (size_t)w * 128 + lane * 4;
    *(uint2*)&g_aggh[idx] = *(uint2*)hb;
    *(uint2*)&g_aggl[idx] = *(uint2*)lb;
}

// ================= weight split (bf16 hi/lo, padded) =================

__global__ void k_wsplit(const float* __restrict__ w1a, const float* __restrict__ w1b,
                         const float* __restrict__ w1c, const float* __restrict__ w2a,
                         const float* __restrict__ w2b, const float* __restrict__ w2c) {
    int i = blockIdx.x * blockDim.x + threadIdx.x;
    if (i >= 3 * 65536) return;
    int l = i / 65536, j = i - l * 65536;
    const float* w1 = (l == 0) ? w1a : (l == 1) ? w1b : w1c;
    const float* w2 = (l == 0) ? w2a : (l == 1) ? w2b : w2c;
    if (j < 32768) {
        int r = j >> 7, c = j & 127;
        float v = (r < 200 && c < 100) ? w1[r * 100 + c] : 0.0f;
        __nv_bfloat16 h, lo; bsplit(v, h, lo);
        g_w1h[l][j] = h; g_w1l[l][j] = lo;
    } else {
        int jj = j - 32768;
        int r = jj >> 8, c = jj & 255;
        float v = (r < 100 && c < 200) ? w2[r * 200 + c] : 0.0f;
        __nv_bfloat16 h, lo; bsplit(v, h, lo);
        g_w2h[l][jj] = h; g_w2l[l][jj] = lo;
    }
}

// ================= graph-level node CSR =================

__global__ void k_gscan() {
    int tid = threadIdx.x;
    int v = g_cntg[tid];
    int lane = tid & 31, w = tid >> 5;
    int x = v;
#pragma unroll
    for (int o = 1; o < 32; o <<= 1) {
        int t = __shfl_up_sync(0xffffffffu, x, o);
        if (lane >= o) x += t;
    }
    __shared__ int ws[16];
    if (lane == 31) ws[w] = x;
    __syncthreads();
    int add = 0;
    for (int k = 0; k < w; k++) add += ws[k];
    g_goff[tid] = add + x - v;
    g_gcur[tid] = add + x - v;
    if (tid == 511) g_goff[512] = add + x;
}

__global__ void k_gscatter(const int* __restrict__ batch) {
    int n = blockIdx.x * blockDim.x + threadIdx.x;
    if (n < NN) {
        int g = clampi(batch[n], GG);
        int p = atomicAdd(&g_gcur[g], 1);
        if (p >= 0 && p < NN) g_nlist[p] = n;
    }
    if (n < GG) g_cntg[n] = 0;
}

// ============ fused MLP: GEMM1 -> smem hid -> GEMM2, 3-deep cp.async ring ============
// Stages 0..3: phase1 (A=agg kc-chunk, B=w1 nb-half). Stages 4..7: phase2 (B=w2 k-chunk).
// hid[64][200] lives in smem bf16 split planes (pitch 216), never touches DRAM.

__device__ __forceinline__ void cpa_plane(uint32_t sdst, const __nv_bfloat16* __restrict__ src,
                                          int row0, int rowmax, int col0, int pitch, int nrows) {
    int tot = nrows << 3;
    for (int idx = threadIdx.x; idx < tot; idx += 256) {
        int r = idx >> 3, c8 = (idx & 7) << 3;
        const __nv_bfloat16* g = src + (size_t)(row0 + r) * pitch + col0 + c8;
        uint32_t sa = sdst + (uint32_t)(r * PA2 + c8) * 2u;
        int sz = (row0 + r < rowmax) ? 16 : 0;
        asm volatile("cp.async.cg.shared.global [%0], [%1], 16, %2;"
                     :: "r"(sa), "l"(g), "r"(sz));
    }
}

__device__ __forceinline__ void issue_fused(int s, uint32_t bufbase,
        const __nv_bfloat16* Ah, const __nv_bfloat16* Al,
        const __nv_bfloat16* B1h, const __nv_bfloat16* B1l,
        const __nv_bfloat16* B2h, const __nv_bfloat16* B2l, int brow) {
    if (s < 4) {
        int kc = s & 1, nb = s >> 1;
        cpa_plane(bufbase + OAH, Ah, brow, NN, kc * 64, 128, 64);
        cpa_plane(bufbase + OAL, Al, brow, NN, kc * 64, 128, 64);
        cpa_plane(bufbase + OBH, B1h, nb * 128, 1 << 30, kc * 64, 128, 128);
        cpa_plane(bufbase + OBL, B1l, nb * 128, 1 << 30, kc * 64, 128, 128);
    } else {
        int c = s - 4;
        cpa_plane(bufbase + OBH, B2h, 0, 1 << 30, c * 64, 256, 128);
        cpa_plane(bufbase + OBL, B2l, 0, 1 << 30, c * 64, 256, 128);
    }
    asm volatile("cp.async.commit_group;");
}

template <int NKS>
__device__ __forceinline__ void compute_gen(float acc[8][4],
        uint32_t aH, uint32_t aL, int apitch, int ak0,
        uint32_t bH, uint32_t bL, int R0, int N0, int lane) {
#pragma unroll
    for (int ks = 0; ks < NKS; ks++) {
        int k0 = ks * 16;
        uint32_t ah[4], al[4];
        LDSM4(ah, a_addr(aH, R0, ak0 + k0, lane, apitch));
        LDSM4(al, a_addr(aL, R0, ak0 + k0, lane, apitch));
        uint32_t bh[4][4], bl[4][4];
#pragma unroll
        for (int j = 0; j < 4; j++) {
            LDSM4(bh[j], b_addr(bH, N0 + j * 16, k0, lane));
            LDSM4(bl[j], b_addr(bL, N0 + j * 16, k0, lane));
        }
#pragma unroll
        for (int j = 0; j < 4; j++) {
            mma_bf16(acc[2 * j],     ah, &bh[j][0]);
            mma_bf16(acc[2 * j + 1], ah, &bh[j][2]);
            mma_bf16(acc[2 * j],     ah, &bl[j][0]);
            mma_bf16(acc[2 * j + 1], ah, &bl[j][2]);
            mma_bf16(acc[2 * j],     al, &bh[j][0]);
            mma_bf16(acc[2 * j + 1], al, &bh[j][2]);
        }
    }
}

__global__ void __launch_bounds__(256)
k_mmaf(const __nv_bfloat16* __restrict__ B1h, const __nv_bfloat16* __restrict__ B1l,
       const __nv_bfloat16* __restrict__ B2h, const __nv_bfloat16* __restrict__ B2l,
       const float* __restrict__ b1, const float* __restrict__ bng,
       const float* __restrict__ bnb, const float* __restrict__ b2) {
    extern __shared__ char sm[];
    int tid = threadIdx.x, lane = tid & 31, wid = tid >> 5;
    int wm = wid & 3, wn = wid >> 2;
    int R0 = wm * 16, N0 = wn * 64;
    int brow = blockIdx.x * 64;
    uint32_t u0 = smem_u32(sm);
    uint32_t hH = u0 + 3 * BUF;          // hid hi plane (64 x 216 bf16)
    uint32_t hL = hH + HPLB;             // hid lo plane
    __nv_bfloat16* hHp = (__nv_bfloat16*)(sm + 3 * BUF);
    __nv_bfloat16* hLp = (__nv_bfloat16*)(sm + 3 * BUF + HPLB);

    // zero hid pad cols 200..215 (read by phase-2 chunk 3)
    for (int i = tid; i < 64 * 16; i += 256) {
        int r = i >> 4, c = 200 + (i & 15);
        hHp[r * HPA + c] = __nv_bfloat16(0.0f);
        hLp[r * HPA + c] = __nv_bfloat16(0.0f);
    }

    issue_fused(0, u0 + 0 * BUF, g_aggh, g_aggl, B1h, B1l, B2h, B2l, brow);
    issue_fused(1, u0 + 1 * BUF, g_aggh, g_aggl, B1h, B1l, B2h, B2l, brow);
    issue_fused(2, u0 + 2 * BUF, g_aggh, g_aggl, B1h, B1l, B2h, B2l, brow);

    float acc[8][4];
    const float bnscale = rsqrtf(1.0f + 1e-5f);

    for (int s = 0; s < 8; s++) {
        if (s <= 5)      asm volatile("cp.async.wait_group 2;");
        else if (s == 6) asm volatile("cp.async.wait_group 1;");
        else             asm volatile("cp.async.wait_group 0;");
        __syncthreads();

        uint32_t bb = u0 + (s % 3) * BUF;
        if (s < 4) {
            // -------- phase 1: hid = relu(BN(agg @ w1^T + b1)) --------
            if ((s & 1) == 0) {
#pragma unroll
                for (int j = 0; j < 8; j++)
#pragma unroll
                    for (int q = 0; q < 4; q++) acc[j][q] = 0.0f;
            }
            if (s & 1) compute_gen<3>(acc, bb + OAH, bb + OAL, PA2, 0, bb + OBH, bb + OBL, R0, N0, lane);
            else       compute_gen<4>(acc, bb + OAH, bb + OAL, PA2, 0, bb + OBH, bb + OBL, R0, N0, lane);
            if (s & 1) {
                int nb = s >> 1;
                int rl = R0 + (lane >> 2);
#pragma unroll
                for (int j = 0; j < 8; j++) {
                    int ch0 = nb * 128 + N0 + j * 8 + (lane & 3) * 2;
                    if (ch0 >= 200) continue;
                    float c0 = b1[ch0], s0 = bng[ch0] * bnscale, e0 = bnb[ch0];
                    float c1 = 0, s1 = 0, e1 = 0;
                    if (ch0 + 1 < 200) { c1 = b1[ch0 + 1]; s1 = bng[ch0 + 1] * bnscale; e1 = bnb[ch0 + 1]; }
#pragma unroll
                    for (int half = 0; half < 2; half++) {
                        int r = rl + half * 8;
                        float v0 = fmaxf((acc[j][half * 2] + c0) * s0 + e0, 0.0f);
                        float v1 = fmaxf((acc[j][half * 2 + 1] + c1) * s1 + e1, 0.0f);
                        __nv_bfloat16 h0, l0, h1, l1;
                        bsplit(v0, h0, l0); bsplit(v1, h1, l1);
                        *(__nv_bfloat162*)&hHp[r * HPA + ch0] = __nv_bfloat162(h0, h1);
                        *(__nv_bfloat162*)&hLp[r * HPA + ch0] = __nv_bfloat162(l0, l1);
                    }
                }
            }
        } else {
            // -------- phase 2: h = relu(hid @ w2^T + b2), A from smem hid --------
            if (s == 4) {
#pragma unroll
                for (int j = 0; j < 8; j++)
#pragma unroll
                    for (int q = 0; q < 4; q++) acc[j][q] = 0.0f;
            }
            int ak0 = (s - 4) * 64;
            if (s == 7) compute_gen<1>(acc, hH, hL, HPA, ak0, bb + OBH, bb + OBL, R0, N0, lane);
            else        compute_gen<4>(acc, hH, hL, HPA, ak0, bb + OBH, bb + OBL, R0, N0, lane);
            if (s == 7) {
                int r0 = brow + R0 + (lane >> 2);
#pragma unroll
                for (int j = 0; j < 8; j++) {
                    int ch0 = N0 + j * 8 + (lane & 3) * 2;
                    if (ch0 >= 100) continue;
                    float c0 = b2[ch0];
                    float c1 = (ch0 + 1 < 100) ? b2[ch0 + 1] : 0.0f;
#pragma unroll
                    for (int half = 0; half < 2; half++) {
                        int r = r0 + half * 8;
                        if (r >= NN) continue;
                        g_h[(size_t)r * 100 + ch0] = fmaxf(acc[j][half * 2] + c0, 0.0f);
                        if (ch0 + 1 < 100)
                            g_h[(size_t)r * 100 + ch0 + 1] =
                                fmaxf(acc[j][half * 2 + 1] + c1, 0.0f);
                    }
                }
            }
        }
        __syncthreads();
        if (s + 3 <= 7)
            issue_fused(s + 3, u0 + ((s + 3) % 3) * BUF, g_aggh, g_aggl, B1h, B1l, B2h, B2l, brow);
    }
}

// ================= readout =================

__global__ void k_readout_g() {  // grid GG, 256 threads
    int g = blockIdx.x;
    int tid = threadIdx.x, grp = tid >> 5, lane = tid & 31;
    int s0 = g_goff[g];
    int cnt = g_goff[g + 1] - s0;
    float4 sum = make_float4(0, 0, 0, 0), mx = make_float4(0, 0, 0, 0);
    if (lane < 25) {
        for (int i = grp; i < cnt; i += 8) {
            int n = g_nlist[s0 + i];
            float4 v = ((const float4*)g_h)[(size_t)n * 25 + lane];
            sum.x += v.x; sum.y += v.y; sum.z += v.z; sum.w += v.w;
            mx.x = fmaxf(mx.x, v.x); mx.y = fmaxf(mx.y, v.y);
            mx.z = fmaxf(mx.z, v.z); mx.w = fmaxf(mx.w, v.w);
        }
    }
    __shared__ float4 ssum[8][25], smax[8][25];
    if (lane < 25) { ssum[grp][lane] = sum; smax[grp][lane] = mx; }
    __syncthreads();
    if (tid < 25) {
        float4 s = ssum[0][tid], m = smax[0][tid];
        for (int k = 1; k < 8; k++) {
            float4 a = ssum[k][tid], b = smax[k][tid];
            s.x += a.x; s.y += a.y; s.z += a.z; s.w += a.w;
            m.x = fmaxf(m.x, b.x); m.y = fmaxf(m.y, b.y);
            m.z = fmaxf(m.z, b.z); m.w = fmaxf(m.w, b.w);
        }
        float inv = 1.0f / fmaxf((float)cnt, 1.0f);
        int base = g * 200 + tid * 4;
        g_enc[base + 0] += s.x * inv; g_enc[base + 1] += s.y * inv;
        g_enc[base + 2] += s.z * inv; g_enc[base + 3] += s.w * inv;
        g_enc[base + 100] += m.x; g_enc[base + 101] += m.y;
        g_enc[base + 102] += m.z; g_enc[base + 103] += m.w;
    }
}

// ================= fused head =================

__global__ void k_head(const float* __restrict__ fw, const float* __restrict__ fb,
                       const float* __restrict__ cw, const float* __restrict__ cb,
                       float* __restrict__ out) {
    __shared__ float senc[200], sz[100];
    int g = blockIdx.x, tid = threadIdx.x;
    for (int i = tid; i < 200; i += 128) {
        float e = g_enc[g * 200 + i];
        senc[i] = e;
        out[1024 + g * 200 + i] = e;
        g_enc[g * 200 + i] = 0.0f;
    }
    __syncthreads();
    if (tid < 100) {
        float a = fb[tid];
        const float* wr = fw + tid * 200;
#pragma unroll 4
        for (int k = 0; k < 200; k++) a += senc[k] * wr[k];
        sz[tid] = fmaxf(a, 0.0f);
    }
    __syncthreads();
    if (tid < 2) {
        float a = cb[tid];
        const float* wr = cw + tid * 100;
#pragma unroll 4
        for (int k = 0; k < 100; k++) a += sz[k] * wr[k];
        out[g * 2 + tid] = a;
    }
}

// ================= launch =================

extern "C" void kernel_launch(void* const* d_in, const int* in_sizes, int n_in,
                              void* d_out, int out_size) {
    const float* x = (const float*)d_in[0];
    const int* ei = (const int*)d_in[1];
    const int* batch = (const int*)d_in[2];
    const float* c1_src_w = (const float*)d_in[3];
    const float* c1_src_b = (const float*)d_in[4];
    const float* c1_dst_w = (const float*)d_in[5];
    const float* c1_dst_b = (const float*)d_in[6];
    const float* cw1[3] = {(const float*)d_in[7],  (const float*)d_in[13], (const float*)d_in[19]};
    const float* cb1[3] = {(const float*)d_in[8],  (const float*)d_in[14], (const float*)d_in[20]};
    const float* cg[3]  = {(const float*)d_in[9],  (const float*)d_in[15], (const float*)d_in[21]};
    const float* cbe[3] = {(const float*)d_in[10], (const float*)d_in[16], (const float*)d_in[22]};
    const float* cw2[3] = {(const float*)d_in[11], (const float*)d_in[17], (const float*)d_in[23]};
    const float* cb2[3] = {(const float*)d_in[12], (const float*)d_in[18], (const float*)d_in[24]};
    const float* fc1_w = (const float*)d_in[25];
    const float* fc1_b = (const float*)d_in[26];
    const float* cls_w = (const float*)d_in[27];
    const float* cls_b = (const float*)d_in[28];
    float* out = (float*)d_out;

    const int T = 256;
    const int SMEMB = 3 * BUF + 2 * HPLB;  // 165,888 + 55,296 = 221,184 bytes
    cudaFuncSetAttribute(k_mmaf, cudaFuncAttributeMaxDynamicSharedMemorySize, SMEMB);

    __nv_bfloat16 *w1h, *w1l, *w2h, *w2l;
    cudaGetSymbolAddress((void**)&w1h, g_w1h);
    cudaGetSymbolAddress((void**)&w1l, g_w1l);
    cudaGetSymbolAddress((void**)&w2h, g_w2h);
    cudaGetSymbolAddress((void**)&w2l, g_w2l);

    // launches 1-4: pre, scan, scatter, agg  (agg profiled at #4)
    k_pre<<<(EE + T - 1) / T, T>>>(x, c1_src_w, c1_src_b, c1_dst_w, c1_dst_b, ei, batch);
    k_scan<<<NB, 1024>>>();
    k_scatter<<<(EE + T - 1) / T, T>>>(ei);
    k_agg<<<(NN * 32 + T - 1) / T, T>>>(1);

    k_wsplit<<<(3 * 65536 + T - 1) / T, T>>>(cw1[0], cw1[1], cw1[2], cw2[0], cw2[1], cw2[2]);
    k_gscan<<<1, 512>>>();
    k_gscatter<<<(NN + T - 1) / T, T>>>(batch);

    for (int l = 0; l < 3; l++) {
        if (l > 0) k_agg<<<(NN * 32 + T - 1) / T, T>>>(0);
        k_mmaf<<<NT2, 256, SMEMB>>>(
            w1h + (size_t)l * 256 * 128, w1l + (size_t)l * 256 * 128,
            w2h + (size_t)l * 128 * 256, w2l + (size_t)l * 128 * 256,
            cb1[l], cg[l], cbe[l], cb2[l]);
        k_readout_g<<<GG, 256>>>();
    }

    k_head<<<GG, 128>>>(fc1_w, fc1_b, cls_w, cls_b, out);
}

// round 16
// speedup vs baseline: 1.1006x; 1.1006x over previous
#include <cuda_runtime.h>
#include <cuda_bf16.h>
#include <cstdint>

#define NN 100000
#define EE 1600000
#define GG 512
#define NB 98           // ceil(NN/1024)
#define NT2 1563        // ceil(NN/64)
#define PA2 72          // smem plane pitch (bf16 elems) for 64-wide K chunks
#define APL 9216        // A plane bytes: 64 * 72 * 2
#define BPL 18432       // B plane bytes: 128 * 72 * 2
#define BUF 55296       // stage buffer: Ah+Al+Bh+Bl
#define OAH 0
#define OAL APL
#define OBH (2 * APL)
#define OBL (2 * APL + BPL)

// fp32 state (unpadded 100-float rows: 40MB planes stay L2-resident; ALWAYS relu'd)
__device__ __align__(16) float g_h[NN * 100];
__device__ __align__(16) float g_xd[NN * 100];
// bf16 split planes (GEMM operands)
__device__ __align__(16) __nv_bfloat16 g_aggh[NN * 128];
__device__ __align__(16) __nv_bfloat16 g_aggl[NN * 128];
__device__ __align__(16) __nv_bfloat16 g_hidh[NN * 256];
__device__ __align__(16) __nv_bfloat16 g_hidl[NN * 256];
__device__ __align__(16) __nv_bfloat16 g_w1h[3][256 * 128];
__device__ __align__(16) __nv_bfloat16 g_w1l[3][256 * 128];
__device__ __align__(16) __nv_bfloat16 g_w2h[3][128 * 256];
__device__ __align__(16) __nv_bfloat16 g_w2l[3][128 * 256];
// graph structure
__device__ int   g_cnt[NN];
__device__ int   g_off[NN];
__device__ int   g_cur[NN];
__device__ int   g_csr[EE];
__device__ unsigned long long g_desc[NB];
__device__ int   g_cntg[GG];
__device__ int   g_goff[GG + 1];
__device__ int   g_gcur[GG];
__device__ int   g_nlist[NN];
// readout
__device__ float g_enc[GG * 200];

__device__ __forceinline__ int clampi(int v, int hi) {
    return v < 0 ? 0 : (v >= hi ? hi - 1 : v);
}

__device__ __forceinline__ uint32_t smem_u32(const void* p) {
    uint32_t a;
    asm("{ .reg .u64 t; cvta.to.shared.u64 t, %1; cvt.u32.u64 %0, t; }" : "=r"(a) : "l"(p));
    return a;
}

__device__ __forceinline__ void bsplit(float v, __nv_bfloat16& h, __nv_bfloat16& l) {
    h = __float2bfloat16(v);
    l = __float2bfloat16(v - __bfloat162float(h));
}

__device__ __forceinline__ float fexp2(float v) {
    float r;
    asm("ex2.approx.f32 %0, %1;" : "=f"(r) : "f"(v));
    return r;
}

#define LDSM4(r, a) \
    asm volatile("ldmatrix.sync.aligned.m8n8.x4.shared.b16 {%0,%1,%2,%3},[%4];" \
        : "=r"((r)[0]), "=r"((r)[1]), "=r"((r)[2]), "=r"((r)[3]) : "r"(a))

__device__ __forceinline__ void mma_bf16(float* c, const uint32_t* a, const uint32_t* b) {
    asm volatile(
        "mma.sync.aligned.m16n8k16.row.col.f32.bf16.bf16.f32 "
        "{%0,%1,%2,%3}, {%4,%5,%6,%7}, {%8,%9}, {%0,%1,%2,%3};"
        : "+f"(c[0]), "+f"(c[1]), "+f"(c[2]), "+f"(c[3])
        : "r"(a[0]), "r"(a[1]), "r"(a[2]), "r"(a[3]), "r"(b[0]), "r"(b[1]));
}

__device__ __forceinline__ uint32_t a_addr(uint32_t base, int rbase, int k0, int lane) {
    int grp = lane >> 3, wi = lane & 7;
    int r = rbase + ((grp & 1) << 3) + wi;
    int c = k0 + ((grp >> 1) << 3);
    return base + ((r * PA2 + c) << 1);
}
__device__ __forceinline__ uint32_t b_addr(uint32_t base, int nbase, int k0, int lane) {
    int grp = lane >> 3, wi = lane & 7;
    int nr = nbase + ((grp >> 1) << 3) + wi;
    int c = k0 + ((grp & 1) << 3);
    return base + ((nr * PA2 + c) << 1);
}

// ================= launch #1: fused lin10 + histograms =================

__global__ void k_pre(const float* __restrict__ x,
                      const float* __restrict__ ws, const float* __restrict__ bs,
                      const float* __restrict__ wd, const float* __restrict__ bd,
                      const int* __restrict__ ei, const int* __restrict__ batch) {
    __shared__ float sws[1000], sbs[100], swd[1000], sbd[100];
    int tid = threadIdx.x;
    int gi = blockIdx.x * blockDim.x + tid;
    bool doLin = (blockIdx.x * blockDim.x) < NN;   // block-uniform
    if (doLin) {
        for (int i = tid; i < 1000; i += blockDim.x) { sws[i] = ws[i]; swd[i] = wd[i]; }
        for (int i = tid; i < 100; i += blockDim.x)  { sbs[i] = bs[i]; sbd[i] = bd[i]; }
    }
    if (gi < EE) atomicAdd(&g_cnt[clampi(ei[EE + gi], NN)], 1);
    if (gi < NN) atomicAdd(&g_cntg[clampi(batch[gi], GG)], 1);
    if (!doLin) return;
    __syncthreads();
    if (gi >= NN) return;
    float xr[10];
#pragma unroll
    for (int k = 0; k < 10; k++) xr[k] = x[gi * 10 + k];
    for (int o = 0; o < 100; o++) {
        float a = sbs[o], b = sbd[o];
#pragma unroll
        for (int k = 0; k < 10; k++) {
            a += xr[k] * sws[o * 10 + k];
            b += xr[k] * swd[o * 10 + k];
        }
        g_h[gi * 100 + o] = fmaxf(a, 0.0f);   // lin_src output only consumed via relu()
        g_xd[gi * 100 + o] = b;
    }
}

// ================= launch #2: decoupled-lookback scan =================

__global__ void k_scan() {
    int b = blockIdx.x, tid = threadIdx.x;
    int i = b * 1024 + tid;
    int v = (i < NN) ? g_cnt[i] : 0;
    int lane = tid & 31, w = tid >> 5;
    int x = v;
#pragma unroll
    for (int o = 1; o < 32; o <<= 1) {
        int t = __shfl_up_sync(0xffffffffu, x, o);
        if (lane >= o) x += t;
    }
    __shared__ int ws[32];
    if (lane == 31) ws[w] = x;
    __syncthreads();
    if (tid < 32) {
        int s = ws[tid], y = s;
#pragma unroll
        for (int o = 1; o < 32; o <<= 1) {
            int t = __shfl_up_sync(0xffffffffu, y, o);
            if (tid >= o) y += t;
        }
        ws[tid] = y - s;
    }
    __syncthreads();
    int incl = ws[w] + x;
    __shared__ int s_total, s_prefix;
    if (tid == 1023) s_total = incl;
    __syncthreads();
    if (tid == 0) {
        int total = s_total;
        if (b == 0) {
            *(volatile unsigned long long*)&g_desc[0] = (2ull << 32) | (unsigned)total;
            s_prefix = 0;
        } else {
            *(volatile unsigned long long*)&g_desc[b] = (1ull << 32) | (unsigned)total;
            int pre = 0, j = b - 1;
            while (true) {
                unsigned long long d2 = *(volatile unsigned long long*)&g_desc[j];
                unsigned st = (unsigned)(d2 >> 32);
                if (st == 0) continue;
                pre += (int)(unsigned)d2;
                if (st == 2) break;
                j--;
            }
            *(volatile unsigned long long*)&g_desc[b] = (2ull << 32) | (unsigned)(pre + total);
            s_prefix = pre;
        }
    }
    __syncthreads();
    int excl = s_prefix + incl - v;
    if (i < NN) { g_off[i] = excl; g_cur[i] = excl; }
}

// ================= launch #3: scatter (+ reset for replay) =================

__global__ void k_scatter(const int* __restrict__ ei) {
    int e = blockIdx.x * blockDim.x + threadIdx.x;
    if (e < EE) {
        int d = clampi(ei[EE + e], NN);
        int p = atomicAdd(&g_cur[d], 1);
        if (p >= 0 && p < EE) g_csr[p] = clampi(ei[e], NN);
    }
    if (e < NN) g_cnt[e] = 0;
    if (e < NB) g_desc[e] = 0ull;
}

// ================= launch #4 (PROFILED): softmax aggregation =================
// g_h is always relu'd -> no per-edge fmax. Σ e·(r+ε) = Σ e·r + ε·Σ e (exact).

__global__ void k_agg(int use_gxd) {
    int w = (blockIdx.x * blockDim.x + threadIdx.x) >> 5;
    int lane = threadIdx.x & 31;
    if (w >= NN) return;
    if (lane >= 25) {  // zero K-pad cols 100..127
        int c = 100 + (lane - 25) * 4;
        *(uint2*)&g_aggh[(size_t)w * 128 + c] = make_uint2(0u, 0u);
        *(uint2*)&g_aggl[(size_t)w * 128 + c] = make_uint2(0u, 0u);
        return;
    }
    int start = g_off[w];
    int end = (w < NN - 1) ? g_off[w + 1] : EE;
    const char* hbase = (const char*)g_h;
    const float4* xd4 = use_gxd ? (const float4*)g_xd : (const float4*)g_h;
    const float EPS_MSG = 1e-7f;
    const float EPS_SM = 1e-16f;
    const float L2E = 1.44269504f;
    const float CLMP = 115.0f;
    uint32_t boff = (uint32_t)lane * 16u;

    float4 d = make_float4(0, 0, 0, 0);
    float4 nr = make_float4(0, 0, 0, 0);
    for (int i = start; i < end; i++) {
        uint32_t s = (uint32_t)g_csr[i];
        float4 v = *(const float4*)(hbase + s * 400u + boff);
        float e0 = fexp2(fminf(v.x * L2E, CLMP));
        float e1 = fexp2(fminf(v.y * L2E, CLMP));
        float e2 = fexp2(fminf(v.z * L2E, CLMP));
        float e3 = fexp2(fminf(v.w * L2E, CLMP));
        d.x += e0; nr.x = fmaf(e0, v.x, nr.x);
        d.y += e1; nr.y = fmaf(e1, v.y, nr.y);
        d.z += e2; nr.z = fmaf(e2, v.z, nr.z);
        d.w += e3; nr.w = fmaf(e3, v.w, nr.w);
    }
    float4 xv = xd4[(size_t)w * 25 + lane];
    float o0 = fmaf(EPS_MSG, d.x, nr.x) / (d.x + EPS_SM) + xv.x;
    float o1 = fmaf(EPS_MSG, d.y, nr.y) / (d.y + EPS_SM) + xv.y;
    float o2 = fmaf(EPS_MSG, d.z, nr.z) / (d.z + EPS_SM) + xv.z;
    float o3 = fmaf(EPS_MSG, d.w, nr.w) / (d.w + EPS_SM) + xv.w;
    __nv_bfloat16 hb[4], lb[4];
    bsplit(o0, hb[0], lb[0]); bsplit(o1, hb[1], lb[1]);
    bsplit(o2, hb[2], lb[2]); bsplit(o3, hb[3], lb[3]);
    size_t idx = (size_t)w * 128 + lane * 4;
    *(uint2*)&g_aggh[idx] = *(uint2*)hb;
    *(uint2*)&g_aggl[idx] = *(uint2*)lb;
}

// ================= weight split (bf16 hi/lo, padded) =================

__global__ void k_wsplit(const float* __restrict__ w1a, const float* __restrict__ w1b,
                         const float* __restrict__ w1c, const float* __restrict__ w2a,
                         const float* __restrict__ w2b, const float* __restrict__ w2c) {
    int i = blockIdx.x * blockDim.x + threadIdx.x;
    if (i >= 3 * 65536) return;
    int l = i / 65536, j = i - l * 65536;
    const float* w1 = (l == 0) ? w1a : (l == 1) ? w1b : w1c;
    const float* w2 = (l == 0) ? w2a : (l == 1) ? w2b : w2c;
    if (j < 32768) {
        int r = j >> 7, c = j & 127;
        float v = (r < 200 && c < 100) ? w1[r * 100 + c] : 0.0f;
        __nv_bfloat16 h, lo; bsplit(v, h, lo);
        g_w1h[l][j] = h; g_w1l[l][j] = lo;
    } else {
        int jj = j - 32768;
        int r = jj >> 8, c = jj & 255;
        float v = (r < 100 && c < 200) ? w2[r * 200 + c] : 0.0f;
        __nv_bfloat16 h, lo; bsplit(v, h, lo);
        g_w2h[l][jj] = h; g_w2l[l][jj] = lo;
    }
}

// ================= graph-level node CSR =================

__global__ void k_gscan() {
    int tid = threadIdx.x;
    int v = g_cntg[tid];
    int lane = tid & 31, w = tid >> 5;
    int x = v;
#pragma unroll
    for (int o = 1; o < 32; o <<= 1) {
        int t = __shfl_up_sync(0xffffffffu, x, o);
        if (lane >= o) x += t;
    }
    __shared__ int ws[16];
    if (lane == 31) ws[w] = x;
    __syncthreads();
    int add = 0;
    for (int k = 0; k < w; k++) add += ws[k];
    g_goff[tid] = add + x - v;
    g_gcur[tid] = add + x - v;
    if (tid == 511) g_goff[512] = add + x;
}

__global__ void k_gscatter(const int* __restrict__ batch) {
    int n = blockIdx.x * blockDim.x + threadIdx.x;
    if (n < NN) {
        int g = clampi(batch[n], GG);
        int p = atomicAdd(&g_gcur[g], 1);
        if (p >= 0 && p < NN) g_nlist[p] = n;
    }
    if (n < GG) g_cntg[n] = 0;
}

// ================= HMMA split-bf16 GEMM, cp.async pipelined, M=64, 2 CTA/SM =================

__device__ __forceinline__ void cpa_plane(uint32_t sdst, const __nv_bfloat16* __restrict__ src,
                                          int row0, int rowmax, int col0, int pitch, int nrows) {
    int tot = nrows << 3;
    for (int idx = threadIdx.x; idx < tot; idx += 256) {
        int r = idx >> 3, c8 = (idx & 7) << 3;
        const __nv_bfloat16* g = src + (size_t)(row0 + r) * pitch + col0 + c8;
        uint32_t sa = sdst + (uint32_t)(r * PA2 + c8) * 2u;
        int sz = (row0 + r < rowmax) ? 16 : 0;
        asm volatile("cp.async.cg.shared.global [%0], [%1], 16, %2;"
                     :: "r"(sa), "l"(g), "r"(sz));
    }
}

template <int GEMM>
__device__ __forceinline__ void issue_stage(int s, uint32_t bufbase,
        const __nv_bfloat16* Ah, const __nv_bfloat16* Al,
        const __nv_bfloat16* Bh, const __nv_bfloat16* Bl, int brow) {
    int acol0, apitch, brow0, bcol0, bpitch;
    if (GEMM == 1) {
        int kc = s & 1, nb = s >> 1;
        acol0 = kc * 64; apitch = 128; brow0 = nb * 128; bcol0 = kc * 64; bpitch = 128;
    } else {
        acol0 = s * 64; apitch = 256; brow0 = 0; bcol0 = s * 64; bpitch = 256;
    }
    cpa_plane(bufbase + OAH, Ah, brow, NN, acol0, apitch, 64);
    cpa_plane(bufbase + OAL, Al, brow, NN, acol0, apitch, 64);
    cpa_plane(bufbase + OBH, Bh, brow0, 1 << 30, bcol0, bpitch, 128);
    cpa_plane(bufbase + OBL, Bl, brow0, 1 << 30, bcol0, bpitch, 128);
    asm volatile("cp.async.commit_group;");
}

template <int NKS>
__device__ __forceinline__ void compute_chunk(float acc[8][4], uint32_t bb,
                                              int R0, int N0, int lane) {
#pragma unroll
    for (int ks = 0; ks < NKS; ks++) {
        int k0 = ks * 16;
        uint32_t ah[4], al[4];
        LDSM4(ah, a_addr(bb + OAH, R0, k0, lane));
        LDSM4(al, a_addr(bb + OAL, R0, k0, lane));
        uint32_t bh[4][4], bl[4][4];
#pragma unroll
        for (int j = 0; j < 4; j++) {
            LDSM4(bh[j], b_addr(bb + OBH, N0 + j * 16, k0, lane));
            LDSM4(bl[j], b_addr(bb + OBL, N0 + j * 16, k0, lane));
        }
#pragma unroll
        for (int j = 0; j < 4; j++) {
            mma_bf16(acc[2 * j],     ah, &bh[j][0]);
            mma_bf16(acc[2 * j + 1], ah, &bh[j][2]);
            mma_bf16(acc[2 * j],     ah, &bl[j][0]);
            mma_bf16(acc[2 * j + 1], ah, &bl[j][2]);
            mma_bf16(acc[2 * j],     al, &bh[j][0]);
            mma_bf16(acc[2 * j + 1], al, &bh[j][2]);
        }
    }
}

template <int GEMM>
__global__ void __launch_bounds__(256, 2)
k_mma(const __nv_bfloat16* __restrict__ Ah, const __nv_bfloat16* __restrict__ Al,
      const __nv_bfloat16* __restrict__ Bh, const __nv_bfloat16* __restrict__ Bl,
      const float* __restrict__ bias, const float* __restrict__ bng,
      const float* __restrict__ bnb) {
    extern __shared__ __nv_bfloat16 sm[];
    int tid = threadIdx.x, lane = tid & 31, wid = tid >> 5;
    int wm = wid & 3, wn = wid >> 2;
    int R0 = wm * 16, N0 = wn * 64;
    int brow = blockIdx.x * 64;
    uint32_t u0 = smem_u32(sm);

    float acc[8][4];

    issue_stage<GEMM>(0, u0, Ah, Al, Bh, Bl, brow);

    for (int s = 0; s < 4; s++) {
        if (s < 3) {
            issue_stage<GEMM>(s + 1, u0 + ((s + 1) & 1) * BUF, Ah, Al, Bh, Bl, brow);
            asm volatile("cp.async.wait_group 1;");
        } else {
            asm volatile("cp.async.wait_group 0;");
        }
        __syncthreads();

        bool reset = (GEMM == 1) ? ((s & 1) == 0) : (s == 0);
        if (reset) {
#pragma unroll
            for (int j = 0; j < 8; j++)
#pragma unroll
                for (int q = 0; q < 4; q++) acc[j][q] = 0.0f;
        }
        uint32_t bb = u0 + (s & 1) * BUF;
        // skip all-zero K padding: GEMM1 kc=1 real K ends at 100-64=36 -> 3 sub-chunks;
        // GEMM2 stage 3 real K ends at 200-192=8 -> 1 sub-chunk.
        if (GEMM == 1) {
            if (s & 1) compute_chunk<3>(acc, bb, R0, N0, lane);
            else       compute_chunk<4>(acc, bb, R0, N0, lane);
        } else {
            if (s == 3) compute_chunk<1>(acc, bb, R0, N0, lane);
            else        compute_chunk<4>(acc, bb, R0, N0, lane);
        }

        bool epi = (GEMM == 1) ? ((s & 1) == 1) : (s == 3);
        if (epi) {
            int r0 = brow + R0 + (lane >> 2);
            if (GEMM == 1) {
                int nb = s >> 1;
                const float bnscale = rsqrtf(1.0f + 1e-5f);
#pragma unroll
                for (int j = 0; j < 8; j++) {
                    int ch0 = nb * 128 + N0 + j * 8 + (lane & 3) * 2;
                    float b0 = 0, b1 = 0, s0 = 0, s1 = 0, e0 = 0, e1 = 0;
                    if (ch0 < 200) { b0 = bias[ch0]; s0 = bng[ch0] * bnscale; e0 = bnb[ch0]; }
                    if (ch0 + 1 < 200) { b1 = bias[ch0 + 1]; s1 = bng[ch0 + 1] * bnscale; e1 = bnb[ch0 + 1]; }
#pragma unroll
                    for (int half = 0; half < 2; half++) {
                        int r = r0 + half * 8;
                        if (r >= NN) continue;
                        float v0 = fmaxf((acc[j][half * 2] + b0) * s0 + e0, 0.0f);
                        float v1 = fmaxf((acc[j][half * 2 + 1] + b1) * s1 + e1, 0.0f);
                        __nv_bfloat16 h0, l0, h1, l1;
                        bsplit(v0, h0, l0); bsplit(v1, h1, l1);
                        size_t o = (size_t)r * 256 + ch0;
                        *(__nv_bfloat162*)&g_hidh[o] = __nv_bfloat162(h0, h1);
                        *(__nv_bfloat162*)&g_hidl[o] = __nv_bfloat162(l0, l1);
                    }
                }
            } else {
#pragma unroll
                for (int j = 0; j < 8; j++) {
                    int ch0 = N0 + j * 8 + (lane & 3) * 2;
                    if (ch0 >= 100) continue;
                    float b0 = bias[ch0];
                    float b1 = (ch0 + 1 < 100) ? bias[ch0 + 1] : 0.0f;
#pragma unroll
                    for (int half = 0; half < 2; half++) {
                        int r = r0 + half * 8;
                        if (r >= NN) continue;
                        g_h[(size_t)r * 100 + ch0] = fmaxf(acc[j][half * 2] + b0, 0.0f);
                        if (ch0 + 1 < 100)
                            g_h[(size_t)r * 100 + ch0 + 1] =
                                fmaxf(acc[j][half * 2 + 1] + b1, 0.0f);
                    }
                }
            }
        }
        __syncthreads();
    }
}

// ================= readout =================

__global__ void k_readout_g() {  // grid GG, 256 threads
    int g = blockIdx.x;
    int tid = threadIdx.x, grp = tid >> 5, lane = tid & 31;
    int s0 = g_goff[g];
    int cnt = g_goff[g + 1] - s0;
    float4 sum = make_float4(0, 0, 0, 0), mx = make_float4(0, 0, 0, 0);
    if (lane < 25) {
        for (int i = grp; i < cnt; i += 8) {
            int n = g_nlist[s0 + i];
            float4 v = ((const float4*)g_h)[(size_t)n * 25 + lane];
            sum.x += v.x; sum.y += v.y; sum.z += v.z; sum.w += v.w;
            mx.x = fmaxf(mx.x, v.x); mx.y = fmaxf(mx.y, v.y);
            mx.z = fmaxf(mx.z, v.z); mx.w = fmaxf(mx.w, v.w);
        }
    }
    __shared__ float4 ssum[8][25], smax[8][25];
    if (lane < 25) { ssum[grp][lane] = sum; smax[grp][lane] = mx; }
    __syncthreads();
    if (tid < 25) {
        float4 s = ssum[0][tid], m = smax[0][tid];
        for (int k = 1; k < 8; k++) {
            float4 a = ssum[k][tid], b = smax[k][tid];
            s.x += a.x; s.y += a.y; s.z += a.z; s.w += a.w;
            m.x = fmaxf(m.x, b.x); m.y = fmaxf(m.y, b.y);
            m.z = fmaxf(m.z, b.z); m.w = fmaxf(m.w, b.w);
        }
        float inv = 1.0f / fmaxf((float)cnt, 1.0f);
        int base = g * 200 + tid * 4;
        g_enc[base + 0] += s.x * inv; g_enc[base + 1] += s.y * inv;
        g_enc[base + 2] += s.z * inv; g_enc[base + 3] += s.w * inv;
        g_enc[base + 100] += m.x; g_enc[base + 101] += m.y;
        g_enc[base + 102] += m.z; g_enc[base + 103] += m.w;
    }
}

// ================= fused head =================

__global__ void k_head(const float* __restrict__ fw, const float* __restrict__ fb,
                       const float* __restrict__ cw, const float* __restrict__ cb,
                       float* __restrict__ out) {
    __shared__ float senc[200], sz[100];
    int g = blockIdx.x, tid = threadIdx.x;
    for (int i = tid; i < 200; i += 128) {
        float e = g_enc[g * 200 + i];
        senc[i] = e;
        out[1024 + g * 200 + i] = e;
        g_enc[g * 200 + i] = 0.0f;
    }
    __syncthreads();
    if (tid < 100) {
        float a = fb[tid];
        const float* wr = fw + tid * 200;
#pragma unroll 4
        for (int k = 0; k < 200; k++) a += senc[k] * wr[k];
        sz[tid] = fmaxf(a, 0.0f);
    }
    __syncthreads();
    if (tid < 2) {
        float a = cb[tid];
        const float* wr = cw + tid * 100;
#pragma unroll 4
        for (int k = 0; k < 100; k++) a += sz[k] * wr[k];
        out[g * 2 + tid] = a;
    }
}

// ================= launch =================

extern "C" void kernel_launch(void* const* d_in, const int* in_sizes, int n_in,
                              void* d_out, int out_size) {
    const float* x = (const float*)d_in[0];
    const int* ei = (const int*)d_in[1];
    const int* batch = (const int*)d_in[2];
    const float* c1_src_w = (const float*)d_in[3];
    const float* c1_src_b = (const float*)d_in[4];
    const float* c1_dst_w = (const float*)d_in[5];
    const float* c1_dst_b = (const float*)d_in[6];
    const float* cw1[3] = {(const float*)d_in[7],  (const float*)d_in[13], (const float*)d_in[19]};
    const float* cb1[3] = {(const float*)d_in[8],  (const float*)d_in[14], (const float*)d_in[20]};
    const float* cg[3]  = {(const float*)d_in[9],  (const float*)d_in[15], (const float*)d_in[21]};
    const float* cbe[3] = {(const float*)d_in[10], (const float*)d_in[16], (const float*)d_in[22]};
    const float* cw2[3] = {(const float*)d_in[11], (const float*)d_in[17], (const float*)d_in[23]};
    const float* cb2[3] = {(const float*)d_in[12], (const float*)d_in[18], (const float*)d_in[24]};
    const float* fc1_w = (const float*)d_in[25];
    const float* fc1_b = (const float*)d_in[26];
    const float* cls_w = (const float*)d_in[27];
    const float* cls_b = (const float*)d_in[28];
    float* out = (float*)d_out;

    const int T = 256;
    const int SMEMB = 2 * BUF;  // 110,592 bytes -> 2 CTA/SM
    cudaFuncSetAttribute(k_mma<1>, cudaFuncAttributeMaxDynamicSharedMemorySize, SMEMB);
    cudaFuncSetAttribute(k_mma<2>, cudaFuncAttributeMaxDynamicSharedMemorySize, SMEMB);

    __nv_bfloat16 *aggh, *aggl, *hidh, *hidl, *w1h, *w1l, *w2h, *w2l;
    cudaGetSymbolAddress((void**)&aggh, g_aggh);
    cudaGetSymbolAddress((void**)&aggl, g_aggl);
    cudaGetSymbolAddress((void**)&hidh, g_hidh);
    cudaGetSymbolAddress((void**)&hidl, g_hidl);
    cudaGetSymbolAddress((void**)&w1h, g_w1h);
    cudaGetSymbolAddress((void**)&w1l, g_w1l);
    cudaGetSymbolAddress((void**)&w2h, g_w2h);
    cudaGetSymbolAddress((void**)&w2l, g_w2l);

    // launches 1-4: pre, scan, scatter, agg  (agg profiled at #4)
    k_pre<<<(EE + T - 1) / T, T>>>(x, c1_src_w, c1_src_b, c1_dst_w, c1_dst_b, ei, batch);
    k_scan<<<NB, 1024>>>();
    k_scatter<<<(EE + T - 1) / T, T>>>(ei);
    k_agg<<<(NN * 32 + T - 1) / T, T>>>(1);

    k_wsplit<<<(3 * 65536 + T - 1) / T, T>>>(cw1[0], cw1[1], cw1[2], cw2[0], cw2[1], cw2[2]);
    k_gscan<<<1, 512>>>();
    k_gscatter<<<(NN + T - 1) / T, T>>>(batch);

    for (int l = 0; l < 3; l++) {
        if (l > 0) k_agg<<<(NN * 32 + T - 1) / T, T>>>(0);
        k_mma<1><<<NT2, 256, SMEMB>>>(aggh, aggl,
            w1h + (size_t)l * 256 * 128, w1l + (size_t)l * 256 * 128,
            cb1[l], cg[l], cbe[l]);
        k_mma<2><<<NT2, 256, SMEMB>>>(hidh, hidl,
            w2h + (size_t)l * 128 * 256, w2l + (size_t)l * 128 * 256,
            cb2[l], nullptr, nullptr);
        k_readout_g<<<GG, 256>>>();
    }

    k_head<<<GG, 128>>>(fc1_w, fc1_b, cls_w, cls_b, out);
}